// round 10
// baseline (speedup 1.0000x reference)
#include <cuda_runtime.h>
#include <stdint.h>

// KVGather: out[n, i, k, w, c] = r_weight[n,i,k] * kv[n, r_idx[n,i,k], w, c]
// N=16, P2=64, TOPK=8, W2=64, C_KV=128. idx int32, weight f32, kv f32. Out 256 MB f32.
//
// R8: RETRY of R7 (broker-level container failure; kernel never ran).
// Writes go through TMA bulk stores (cp.async.bulk shared->global) instead of
// STG.128, removing ~16.8M STG issue slots + their L1tex wavefronts. Loads remain
// LDG (L2-resident kv). Double-buffered 8KB SMEM staging per CTA.

static constexpr int N       = 16;
static constexpr int P2      = 64;
static constexpr int TOPK    = 8;
static constexpr int WC4     = 64 * 128 / 4;   // 2048 float4 per gathered block (32 KB)
static constexpr int SLICES  = 4;
static constexpr int SL4     = WC4 / SLICES;   // 512 float4 = 8 KB per slice
static constexpr int THREADS = 256;            // 2 float4 per thread per slice
static constexpr int SLICE_BYTES = SL4 * 16;   // 8192

__global__ __launch_bounds__(THREADS)
void kv_gather_tma_kernel(const int*    __restrict__ r_idx,
                          const float*  __restrict__ r_weight,
                          const float4* __restrict__ kv4,
                          float4*       __restrict__ out4) {
    __shared__ alignas(128) float4 buf[2][SL4];

    const int g   = blockIdx.x;                 // 0 .. 8191 (one CTA per destination block)
    const int n   = g >> 9;                     // / (P2*TOPK)
    const int tid = threadIdx.x;

    const int   src = r_idx[g] & (P2 - 1);
    const float wt  = r_weight[g];

    const float4* __restrict__ s = kv4  + (long long)(n * P2 + src) * WC4;
    float4*       __restrict__ d = out4 + (long long)g * WC4;

    #pragma unroll
    for (int sl = 0; sl < SLICES; ++sl) {
        const int pb = sl & 1;

        // Before reusing a buffer, make sure its previous bulk-store has read it out.
        if (sl >= 2) {
            if (tid == 0)
                asm volatile("cp.async.bulk.wait_group.read 1;" ::: "memory");
            __syncthreads();
        }

        // Load slice from kv (L2-resident), scale, stage in SMEM.
        const float4* sp = s + sl * SL4;
        float4 v0 = __ldg(sp + tid);
        float4 v1 = __ldg(sp + tid + THREADS);
        v0.x *= wt; v0.y *= wt; v0.z *= wt; v0.w *= wt;
        v1.x *= wt; v1.y *= wt; v1.z *= wt; v1.w *= wt;
        buf[pb][tid]           = v0;
        buf[pb][tid + THREADS] = v1;

        // Order generic-proxy STS before the async-proxy bulk read.
        asm volatile("fence.proxy.async.shared::cta;" ::: "memory");
        __syncthreads();

        if (tid == 0) {
            uint32_t smem_addr = (uint32_t)__cvta_generic_to_shared(&buf[pb][0]);
            asm volatile(
                "cp.async.bulk.global.shared::cta.bulk_group [%0], [%1], %2;"
                :: "l"(d + sl * SL4), "r"(smem_addr), "n"(SLICE_BYTES)
                : "memory");
            asm volatile("cp.async.bulk.commit_group;" ::: "memory");
        }
    }

    // Drain all outstanding bulk stores before exit.
    if (tid == 0)
        asm volatile("cp.async.bulk.wait_group 0;" ::: "memory");
}

extern "C" void kernel_launch(void* const* d_in, const int* in_sizes, int n_in,
                              void* d_out, int out_size) {
    const int*    r_idx    = (const int*)d_in[0];
    const float*  r_weight = (const float*)d_in[1];
    const float4* kv4      = (const float4*)d_in[2];
    float4*       out4     = (float4*)d_out;

    kv_gather_tma_kernel<<<N * P2 * TOPK, THREADS>>>(r_idx, r_weight, kv4, out4);
}